// round 13
// baseline (speedup 1.0000x reference)
#include <cuda_runtime.h>
#include <cuda_bf16.h>
#include <cstdint>

#define B 8
#define N 2048
#define D 128
#define TEMP (1.0f / 13.544f)
#define CLOG (-1.4426950408889634f * TEMP)        /* c = -T*log2(e) < 0 */
#define K2C  (2.0f * 1.4426950408889634f * TEMP)  /* -2c > 0 */

#define PSB 272            /* padded row stride in bytes (136 bf16) */
#define TILE_B 34816       /* 128 * PSB */

// smem layout (bytes)
#define SM_CSJ  0                      /* 2048 floats = 8192 B (all columns) */
#define SM_RED  8192                   /* 256 floats = 1024 B */
#define SM_A    10240
#define SM_B    (SM_A + TILE_B)        /* 4 ring buffers */
#define SM_TOTAL (SM_B + 4 * TILE_B)   /* 184320 */

__device__ __nv_bfloat16 g_xbf[B * N * D];
__device__ float g_sq[B * N];

// ---------------- helpers ----------------
__device__ __forceinline__ uint32_t smem_u32(const void* p) {
    uint32_t a;
    asm("{ .reg .u64 t; cvta.to.shared.u64 t, %1; cvt.u32.u64 %0, t; }"
        : "=r"(a) : "l"(p));
    return a;
}
__device__ __forceinline__ void ldsm_x4(uint32_t* r, uint32_t addr) {
    asm volatile("ldmatrix.sync.aligned.m8n8.x4.shared.b16 {%0,%1,%2,%3}, [%4];"
                 : "=r"(r[0]), "=r"(r[1]), "=r"(r[2]), "=r"(r[3]) : "r"(addr));
}
__device__ __forceinline__ void mma_16816(float* d, const uint32_t* a,
                                          const uint32_t* b) {
    asm volatile(
        "mma.sync.aligned.m16n8k16.row.col.f32.bf16.bf16.f32 "
        "{%0,%1,%2,%3}, {%4,%5,%6,%7}, {%8,%9}, {%0,%1,%2,%3};"
        : "+f"(d[0]), "+f"(d[1]), "+f"(d[2]), "+f"(d[3])
        : "r"(a[0]), "r"(a[1]), "r"(a[2]), "r"(a[3]), "r"(b[0]), "r"(b[1]));
}
__device__ __forceinline__ float ex2(float x) {
    float r;
    asm("ex2.approx.ftz.f32 %0, %1;" : "=f"(r) : "f"(x));
    return r;
}
#define CP16(saddr, gptr) \
    asm volatile("cp.async.cg.shared.global [%0], [%1], 16;" \
                 :: "r"(saddr), "l"(gptr))
#define CP_COMMIT() asm volatile("cp.async.commit_group;" ::: "memory")
#define CP_WAIT(n)  asm volatile("cp.async.wait_group %0;" :: "n"(n) : "memory")

// load B fragments for one k-step (8 n-subtiles of the 64-col band)
__device__ __forceinline__ void load_bfrags(uint32_t bbase, int k, uint32_t bf[8][2]) {
    uint32_t t[4];
    #pragma unroll
    for (int p = 0; p < 4; p++) {
        ldsm_x4(t, bbase + p * 16 * PSB + k * 32);
        bf[2 * p][0] = t[0]; bf[2 * p][1] = t[2];
        bf[2 * p + 1][0] = t[1]; bf[2 * p + 1][1] = t[3];
    }
}

// ---------------------------------------------------------------------------
// Prep: fp32 -> bf16 copy; squared norms from the bf16 values (fp32 accum)
// so the MMA diagonal distance cancels to ~0.
// ---------------------------------------------------------------------------
__global__ void prep_kernel(const float* __restrict__ x) {
    int row = blockIdx.x * 8 + (threadIdx.x >> 5);
    int lane = threadIdx.x & 31;
    float4 v = reinterpret_cast<const float4*>(x + (size_t)row * D)[lane];
    __nv_bfloat16 b0 = __float2bfloat16(v.x), b1 = __float2bfloat16(v.y);
    __nv_bfloat16 b2 = __float2bfloat16(v.z), b3 = __float2bfloat16(v.w);
    uint2 pk;
    pk.x = ((uint32_t)__bfloat16_as_ushort(b1) << 16) | __bfloat16_as_ushort(b0);
    pk.y = ((uint32_t)__bfloat16_as_ushort(b3) << 16) | __bfloat16_as_ushort(b2);
    reinterpret_cast<uint2*>(g_xbf + (size_t)row * D)[lane] = pk;
    float a0 = __bfloat162float(b0), a1 = __bfloat162float(b1);
    float a2 = __bfloat162float(b2), a3 = __bfloat162float(b3);
    float s = a0 * a0 + a1 * a1 + a2 * a2 + a3 * a3;
    #pragma unroll
    for (int o = 16; o; o >>= 1) s += __shfl_xor_sync(0xffffffffu, s, o);
    if (lane == 0) g_sq[row] = s;
}

// ---------------------------------------------------------------------------
// Main kernel: CTA = (batch, 128-row band). 8 warps (4 row x 2 col bands),
// warp tile 32x64. A fragments PERSISTENT in registers (loaded once).
// 32 iterations over 16 j-tiles x 2 passes (pass 0 row sums, pass 1 store).
// 4-deep cp.async ring (one __syncthreads per iteration), k-pipelined B
// fragments, csj for all 2048 columns precomputed once in smem.
// ---------------------------------------------------------------------------
__global__ void __launch_bounds__(256, 1)
sim_mma_kernel(float* __restrict__ out) {
    extern __shared__ char smem[];
    const uint32_t sbase = smem_u32(smem);
    const int tid = threadIdx.x;
    const int wid = tid >> 5, lane = tid & 31;
    const int wm = wid & 3;                // 32-row band within 128
    const int wn = wid >> 2;               // 64-col band within 128
    const int b = blockIdx.y;
    const int i0 = blockIdx.x * 128;

    const __nv_bfloat16* xb = g_xbf + (size_t)b * N * D;
    const float* sqb = g_sq + b * N;
    float* csjall = reinterpret_cast<float*>(smem + SM_CSJ);
    float* red    = reinterpret_cast<float*>(smem + SM_RED);

    // ---- prologue: A + B0 (group 0), B1 (group 1), csj all columns ----
    const int pr = tid >> 1, ph = tid & 1;        // 128 rows x 2 x 128B
    {
        const char* gA = (const char*)(xb + (size_t)(i0 + pr) * D) + ph * 128;
        uint32_t sA = sbase + SM_A + pr * PSB + ph * 128;
        const char* gB0 = (const char*)(xb + (size_t)pr * D) + ph * 128;
        uint32_t sB0 = sbase + SM_B + pr * PSB + ph * 128;
        #pragma unroll
        for (int q = 0; q < 8; q++) {
            CP16(sA + q * 16, gA + q * 16);
            CP16(sB0 + q * 16, gB0 + q * 16);
        }
        CP_COMMIT();                               // group 0: A + B(0)
        const char* gB1 = (const char*)(xb + (size_t)(128 + pr) * D) + ph * 128;
        uint32_t sB1 = sbase + SM_B + TILE_B + pr * PSB + ph * 128;
        #pragma unroll
        for (int q = 0; q < 8; q++) CP16(sB1 + q * 16, gB1 + q * 16);
        CP_COMMIT();                               // group 1: B(1)

        // csj for ALL 2048 columns (plain stores, covered by first sync)
        #pragma unroll
        for (int t2 = 0; t2 < 2; t2++) {
            int idx = tid + t2 * 256;
            float4 sv = reinterpret_cast<const float4*>(sqb)[idx];
            float4 cv;
            cv.x = CLOG * sv.x; cv.y = CLOG * sv.y;
            cv.z = CLOG * sv.z; cv.w = CLOG * sv.w;
            reinterpret_cast<float4*>(csjall)[idx] = cv;
        }
    }

    // per-thread row constants (LDG, independent of smem)
    float csi[2][2], inv[2][2], rsum[2][2];
    #pragma unroll
    for (int m = 0; m < 2; m++)
        #pragma unroll
        for (int s = 0; s < 2; s++) {
            int r = i0 + wm * 32 + m * 16 + (lane >> 2) + s * 8;
            csi[m][s] = CLOG * sqb[r];
            rsum[m][s] = 0.0f;
            inv[m][s] = 0.0f;
        }

    const uint32_t arow = sbase + SM_A + (wm * 32 + (lane & 15)) * PSB + (lane >> 4) * 16;
    const uint32_t bld  = sbase + SM_B + (wn * 64 + (lane & 15)) * PSB + (lane >> 4) * 16;

    uint32_t afrag[8][2][4];   // persistent: 8 k-steps x 2 m-tiles

    for (int tt = 0; tt < 32; tt++) {
        // prefetch B(tt+2) into ring slot (tt+2)&3 (slot last read at tt-2)
        if (tt < 30) {
            const int jn = ((tt + 2) & 15) * 128;
            const char* gB = (const char*)(xb + (size_t)(jn + pr) * D) + ph * 128;
            uint32_t sB = sbase + SM_B + ((tt + 2) & 3) * TILE_B + pr * PSB + ph * 128;
            #pragma unroll
            for (int q = 0; q < 8; q++) CP16(sB + q * 16, gB + q * 16);
            CP_COMMIT();
        }
        if (tt < 30)       CP_WAIT(2);   // B(tt) (and A on tt=0) ready
        else if (tt == 30) CP_WAIT(1);
        else               CP_WAIT(0);
        __syncthreads();                 // all copies + compute(tt-1) done

        // one-time persistent A fragment load (A never re-read after this)
        if (tt == 0) {
            #pragma unroll
            for (int k = 0; k < 8; k++) {
                ldsm_x4(afrag[k][0], arow + k * 32);
                ldsm_x4(afrag[k][1], arow + 16 * PSB + k * 32);
            }
        }

        // ---- MMA: this warp's 32x64 slice, B k-pipelined ----
        float acc[2][8][4];
        #pragma unroll
        for (int m = 0; m < 2; m++)
            #pragma unroll
            for (int n = 0; n < 8; n++)
                #pragma unroll
                for (int e = 0; e < 4; e++) acc[m][n][e] = 0.0f;

        const uint32_t bbase = bld + (tt & 3) * TILE_B;
        uint32_t bf[2][8][2];
        load_bfrags(bbase, 0, bf[0]);
        #pragma unroll
        for (int k = 0; k < 8; k++) {
            const int cur = k & 1;
            if (k < 7) load_bfrags(bbase, k + 1, bf[cur ^ 1]);
            #pragma unroll
            for (int m = 0; m < 2; m++)
                #pragma unroll
                for (int n = 0; n < 8; n++)
                    mma_16816(acc[m][n], afrag[k][m], bf[cur][n]);
        }

        // ---- epilogue ----
        const int j0 = (tt & 15) * 128;
        const int colb = wn * 64 + (lane & 3) * 2;
        float cj[16];
        #pragma unroll
        for (int n = 0; n < 8; n++) {
            float2 t = *reinterpret_cast<const float2*>(csjall + j0 + colb + n * 8);
            cj[2 * n] = t.x; cj[2 * n + 1] = t.y;
        }

        if (tt < 16) {
            #pragma unroll
            for (int m = 0; m < 2; m++) {
                float base0 = csi[m][0], base1 = csi[m][1];
                #pragma unroll
                for (int n = 0; n < 8; n++) {
                    float p0 = ex2(fmaf(K2C, acc[m][n][0], base0 + cj[2 * n]));
                    float p1 = ex2(fmaf(K2C, acc[m][n][1], base0 + cj[2 * n + 1]));
                    float p2 = ex2(fmaf(K2C, acc[m][n][2], base1 + cj[2 * n]));
                    float p3 = ex2(fmaf(K2C, acc[m][n][3], base1 + cj[2 * n + 1]));
                    rsum[m][0] += p0 + p1;
                    rsum[m][1] += p2 + p3;
                }
            }
        } else {
            #pragma unroll
            for (int m = 0; m < 2; m++) {
                const int r0 = i0 + wm * 32 + m * 16 + (lane >> 2);
                float* orow0 = out + (size_t)(b * N + r0) * N + j0 + colb;
                float* orow1 = orow0 + (size_t)8 * N;
                float base0 = csi[m][0], base1 = csi[m][1];
                #pragma unroll
                for (int n = 0; n < 8; n++) {
                    float2 w0, w1;
                    w0.x = ex2(fmaf(K2C, acc[m][n][0], base0 + cj[2 * n]))     * inv[m][0];
                    w0.y = ex2(fmaf(K2C, acc[m][n][1], base0 + cj[2 * n + 1])) * inv[m][0];
                    w1.x = ex2(fmaf(K2C, acc[m][n][2], base1 + cj[2 * n]))     * inv[m][1];
                    w1.y = ex2(fmaf(K2C, acc[m][n][3], base1 + cj[2 * n + 1])) * inv[m][1];
                    *reinterpret_cast<float2*>(orow0 + n * 8) = w0;
                    *reinterpret_cast<float2*>(orow1 + n * 8) = w1;
                }
            }
        }

        // ---- end of pass 0: reduce row sums across the 2 column bands ----
        if (tt == 15) {
            #pragma unroll
            for (int m = 0; m < 2; m++)
                #pragma unroll
                for (int s = 0; s < 2; s++) {
                    float v = rsum[m][s];
                    v += __shfl_xor_sync(0xffffffffu, v, 1);
                    v += __shfl_xor_sync(0xffffffffu, v, 2);
                    if ((lane & 3) == 0)
                        red[wn * 128 + wm * 32 + m * 16 + (lane >> 2) + s * 8] = v;
                }
            __syncthreads();
            #pragma unroll
            for (int m = 0; m < 2; m++)
                #pragma unroll
                for (int s = 0; s < 2; s++) {
                    int rl = wm * 32 + m * 16 + (lane >> 2) + s * 8;
                    inv[m][s] = __fdividef(1.0f, red[rl] + red[128 + rl]);
                }
        }
    }
}

// ---------------------------------------------------------------------------
extern "C" void kernel_launch(void* const* d_in, const int* in_sizes, int n_in,
                              void* d_out, int out_size) {
    const float* x = (const float*)d_in[0];
    float* out = (float*)d_out;

    prep_kernel<<<(B * N) / 8, 256>>>(x);

    cudaFuncSetAttribute(sim_mma_kernel,
                         cudaFuncAttributeMaxDynamicSharedMemorySize, SM_TOTAL);
    dim3 grid(N / 128, B);
    sim_mma_kernel<<<grid, 256, SM_TOTAL>>>(out);
}

// round 14
// speedup vs baseline: 1.1014x; 1.1014x over previous
#include <cuda_runtime.h>
#include <cuda_bf16.h>
#include <cstdint>

#define B 8
#define N 2048
#define D 128
#define TEMP (1.0f / 13.544f)
#define CLOG (-1.4426950408889634f * TEMP)        /* c = -T*log2(e) < 0 */
#define K2C  (2.0f * 1.4426950408889634f * TEMP)  /* -2c > 0 */

#define PSB 272            /* padded row stride in bytes (136 bf16) */
#define TILE_B 34816       /* 128 * PSB */

// smem layout (bytes)
#define SM_CSJ  0                      /* 2048 floats = 8192 B (all columns) */
#define SM_RED  8192                   /* 512 floats = 2048 B */
#define SM_A    10240
#define SM_B    (SM_A + TILE_B)        /* 4 ring buffers */
#define SM_TOTAL (SM_B + 4 * TILE_B)   /* 184320 */

__device__ __nv_bfloat16 g_xbf[B * N * D];
__device__ float g_sq[B * N];

// ---------------- helpers ----------------
__device__ __forceinline__ uint32_t smem_u32(const void* p) {
    uint32_t a;
    asm("{ .reg .u64 t; cvta.to.shared.u64 t, %1; cvt.u32.u64 %0, t; }"
        : "=r"(a) : "l"(p));
    return a;
}
__device__ __forceinline__ void ldsm_x4(uint32_t* r, uint32_t addr) {
    asm volatile("ldmatrix.sync.aligned.m8n8.x4.shared.b16 {%0,%1,%2,%3}, [%4];"
                 : "=r"(r[0]), "=r"(r[1]), "=r"(r[2]), "=r"(r[3]) : "r"(addr));
}
__device__ __forceinline__ void mma_16816(float* d, const uint32_t* a,
                                          const uint32_t* b) {
    asm volatile(
        "mma.sync.aligned.m16n8k16.row.col.f32.bf16.bf16.f32 "
        "{%0,%1,%2,%3}, {%4,%5,%6,%7}, {%8,%9}, {%0,%1,%2,%3};"
        : "+f"(d[0]), "+f"(d[1]), "+f"(d[2]), "+f"(d[3])
        : "r"(a[0]), "r"(a[1]), "r"(a[2]), "r"(a[3]), "r"(b[0]), "r"(b[1]));
}
__device__ __forceinline__ float ex2(float x) {
    float r;
    asm("ex2.approx.ftz.f32 %0, %1;" : "=f"(r) : "f"(x));
    return r;
}
#define CP16(saddr, gptr) \
    asm volatile("cp.async.cg.shared.global [%0], [%1], 16;" \
                 :: "r"(saddr), "l"(gptr))
#define CP_COMMIT() asm volatile("cp.async.commit_group;" ::: "memory")
#define CP_WAIT(n)  asm volatile("cp.async.wait_group %0;" :: "n"(n) : "memory")

// load A+B fragments for one k-step into the given phase buffers (R9 mapping)
__device__ __forceinline__ void load_frags(uint32_t arow, uint32_t bbase, int k,
                                           uint32_t af[2][4], uint32_t bf[4][2]) {
    ldsm_x4(af[0], arow + k * 32);
    ldsm_x4(af[1], arow + 16 * PSB + k * 32);
    uint32_t t[4];
    ldsm_x4(t, bbase + k * 32);
    bf[0][0] = t[0]; bf[0][1] = t[2];
    bf[1][0] = t[1]; bf[1][1] = t[3];
    ldsm_x4(t, bbase + 16 * PSB + k * 32);
    bf[2][0] = t[0]; bf[2][1] = t[2];
    bf[3][0] = t[1]; bf[3][1] = t[3];
}

// ---------------------------------------------------------------------------
// Prep: fp32 -> bf16 copy; squared norms from the bf16 values (fp32 accum)
// so the MMA diagonal distance cancels to ~0.
// ---------------------------------------------------------------------------
__global__ void prep_kernel(const float* __restrict__ x) {
    int row = blockIdx.x * 8 + (threadIdx.x >> 5);
    int lane = threadIdx.x & 31;
    float4 v = reinterpret_cast<const float4*>(x + (size_t)row * D)[lane];
    __nv_bfloat16 b0 = __float2bfloat16(v.x), b1 = __float2bfloat16(v.y);
    __nv_bfloat16 b2 = __float2bfloat16(v.z), b3 = __float2bfloat16(v.w);
    uint2 pk;
    pk.x = ((uint32_t)__bfloat16_as_ushort(b1) << 16) | __bfloat16_as_ushort(b0);
    pk.y = ((uint32_t)__bfloat16_as_ushort(b3) << 16) | __bfloat16_as_ushort(b2);
    reinterpret_cast<uint2*>(g_xbf + (size_t)row * D)[lane] = pk;
    float a0 = __bfloat162float(b0), a1 = __bfloat162float(b1);
    float a2 = __bfloat162float(b2), a3 = __bfloat162float(b3);
    float s = a0 * a0 + a1 * a1 + a2 * a2 + a3 * a3;
    #pragma unroll
    for (int o = 16; o; o >>= 1) s += __shfl_xor_sync(0xffffffffu, s, o);
    if (lane == 0) g_sq[row] = s;
}

// ---------------------------------------------------------------------------
// Main kernel: CTA = (batch, 128-row band). 16 warps (4x4), warp tile 32x32.
// 32 tiles = 16 j-tiles x 2 passes (pass 0 row sums, pass 1 store), processed
// as 16 super-iterations of TWO tiles per CP_WAIT+__syncthreads: prefetch for
// tiles 2ss+2/2ss+3 is issued AFTER the barrier (slots last read at ss-1 are
// provably free), and no barrier separates the two tiles' compute -> warps
// decorrelate and epilogue(tile0) overlaps MMA(tile1) across warps.
// ---------------------------------------------------------------------------
__global__ void __launch_bounds__(512, 1)
sim_mma_kernel(float* __restrict__ out) {
    extern __shared__ char smem[];
    const uint32_t sbase = smem_u32(smem);
    const int tid = threadIdx.x;
    const int wid = tid >> 5, lane = tid & 31;
    const int wm = wid & 3;                // 32-row band within 128
    const int wn = wid >> 2;               // 32-col band within 128
    const int b = blockIdx.y;
    const int i0 = blockIdx.x * 128;

    const __nv_bfloat16* xb = g_xbf + (size_t)b * N * D;
    const float* sqb = g_sq + b * N;
    float* csjall = reinterpret_cast<float*>(smem + SM_CSJ);
    float* red    = reinterpret_cast<float*>(smem + SM_RED);

    // ---- prologue: one group = A + B(0) + B(1); csj for all columns ----
    const int pr = tid >> 2, pc = tid & 3;        // 128 rows x 4 x 64B
    {
        const char* gA = (const char*)(xb + (size_t)(i0 + pr) * D) + pc * 64;
        uint32_t sA = sbase + SM_A + pr * PSB + pc * 64;
        const char* gB0 = (const char*)(xb + (size_t)pr * D) + pc * 64;
        uint32_t sB0 = sbase + SM_B + pr * PSB + pc * 64;
        const char* gB1 = (const char*)(xb + (size_t)(128 + pr) * D) + pc * 64;
        uint32_t sB1 = sbase + SM_B + TILE_B + pr * PSB + pc * 64;
        #pragma unroll
        for (int q = 0; q < 4; q++) {
            CP16(sA + q * 16, gA + q * 16);
            CP16(sB0 + q * 16, gB0 + q * 16);
            CP16(sB1 + q * 16, gB1 + q * 16);
        }
        CP_COMMIT();

        // csj for ALL 2048 columns (plain stores, covered by first sync)
        float4 sv = reinterpret_cast<const float4*>(sqb)[tid];
        float4 cv;
        cv.x = CLOG * sv.x; cv.y = CLOG * sv.y;
        cv.z = CLOG * sv.z; cv.w = CLOG * sv.w;
        reinterpret_cast<float4*>(csjall)[tid] = cv;
    }

    // per-thread row constants (LDG, independent of smem)
    float csi[2][2], inv[2][2], rsum[2][2];
    #pragma unroll
    for (int m = 0; m < 2; m++)
        #pragma unroll
        for (int s = 0; s < 2; s++) {
            int r = i0 + wm * 32 + m * 16 + (lane >> 2) + s * 8;
            csi[m][s] = CLOG * sqb[r];
            rsum[m][s] = 0.0f;
            inv[m][s] = 0.0f;
        }

    const uint32_t arow = sbase + SM_A + (wm * 32 + (lane & 15)) * PSB + (lane >> 4) * 16;
    const uint32_t bld  = sbase + SM_B + (wn * 32 + (lane & 15)) * PSB + (lane >> 4) * 16;

    for (int ss = 0; ss < 16; ss++) {
        CP_WAIT(0);          // B(2ss), B(2ss+1) (and A on ss=0) resident
        __syncthreads();     // + compute(ss-1) fully done on all warps

        // prefetch tiles 2ss+2, 2ss+3 into their ring slots (now provably free)
        if (ss < 15) {
            #pragma unroll
            for (int u = 0; u < 2; u++) {
                const int tile = 2 * ss + 2 + u;
                const int jn = (tile & 15) * 128;
                const char* gB = (const char*)(xb + (size_t)(jn + pr) * D) + pc * 64;
                uint32_t sB = sbase + SM_B + (tile & 3) * TILE_B + pr * PSB + pc * 64;
                #pragma unroll
                for (int q = 0; q < 4; q++) CP16(sB + q * 16, gB + q * 16);
            }
            CP_COMMIT();
        }

        // ---- two tiles, no barrier between them ----
        #pragma unroll
        for (int u = 0; u < 2; u++) {
            const int tile = 2 * ss + u;

            float acc[2][4][4];
            #pragma unroll
            for (int m = 0; m < 2; m++)
                #pragma unroll
                for (int n = 0; n < 4; n++)
                    #pragma unroll
                    for (int e = 0; e < 4; e++) acc[m][n][e] = 0.0f;

            const uint32_t bbase = bld + (tile & 3) * TILE_B;
            uint32_t af[2][2][4], bf[2][4][2];
            load_frags(arow, bbase, 0, af[0], bf[0]);
            #pragma unroll
            for (int k = 0; k < 8; k++) {
                const int cur = k & 1;
                if (k < 7) load_frags(arow, bbase, k + 1, af[cur ^ 1], bf[cur ^ 1]);
                #pragma unroll
                for (int m = 0; m < 2; m++)
                    #pragma unroll
                    for (int n = 0; n < 4; n++)
                        mma_16816(acc[m][n], af[cur][m], bf[cur][n]);
            }

            // ---- epilogue ----
            const int j0 = (tile & 15) * 128;
            const int colb = wn * 32 + (lane & 3) * 2;
            float cj[8];
            #pragma unroll
            for (int n = 0; n < 4; n++) {
                float2 t = *reinterpret_cast<const float2*>(csjall + j0 + colb + n * 8);
                cj[2 * n] = t.x; cj[2 * n + 1] = t.y;
            }

            if (tile < 16) {
                #pragma unroll
                for (int m = 0; m < 2; m++) {
                    float base0 = csi[m][0], base1 = csi[m][1];
                    #pragma unroll
                    for (int n = 0; n < 4; n++) {
                        float p0 = ex2(fmaf(K2C, acc[m][n][0], base0 + cj[2 * n]));
                        float p1 = ex2(fmaf(K2C, acc[m][n][1], base0 + cj[2 * n + 1]));
                        float p2 = ex2(fmaf(K2C, acc[m][n][2], base1 + cj[2 * n]));
                        float p3 = ex2(fmaf(K2C, acc[m][n][3], base1 + cj[2 * n + 1]));
                        rsum[m][0] += p0 + p1;
                        rsum[m][1] += p2 + p3;
                    }
                }
            } else {
                #pragma unroll
                for (int m = 0; m < 2; m++) {
                    const int r0 = i0 + wm * 32 + m * 16 + (lane >> 2);
                    float* orow0 = out + (size_t)(b * N + r0) * N + j0 + colb;
                    float* orow1 = orow0 + (size_t)8 * N;
                    float base0 = csi[m][0], base1 = csi[m][1];
                    #pragma unroll
                    for (int n = 0; n < 4; n++) {
                        float2 w0, w1;
                        w0.x = ex2(fmaf(K2C, acc[m][n][0], base0 + cj[2 * n]))     * inv[m][0];
                        w0.y = ex2(fmaf(K2C, acc[m][n][1], base0 + cj[2 * n + 1])) * inv[m][0];
                        w1.x = ex2(fmaf(K2C, acc[m][n][2], base1 + cj[2 * n]))     * inv[m][1];
                        w1.y = ex2(fmaf(K2C, acc[m][n][3], base1 + cj[2 * n + 1])) * inv[m][1];
                        *reinterpret_cast<float2*>(orow0 + n * 8) = w0;
                        *reinterpret_cast<float2*>(orow1 + n * 8) = w1;
                    }
                }
            }

            // ---- end of pass 0 (tile 15): reduce row sums across col bands ----
            if (tile == 15) {
                #pragma unroll
                for (int m = 0; m < 2; m++)
                    #pragma unroll
                    for (int s = 0; s < 2; s++) {
                        float v = rsum[m][s];
                        v += __shfl_xor_sync(0xffffffffu, v, 1);
                        v += __shfl_xor_sync(0xffffffffu, v, 2);
                        if ((lane & 3) == 0)
                            red[wn * 128 + wm * 32 + m * 16 + (lane >> 2) + s * 8] = v;
                    }
                __syncthreads();
                #pragma unroll
                for (int m = 0; m < 2; m++)
                    #pragma unroll
                    for (int s = 0; s < 2; s++) {
                        int rl = wm * 32 + m * 16 + (lane >> 2) + s * 8;
                        inv[m][s] = __fdividef(1.0f, red[rl] + red[128 + rl] +
                                                     red[256 + rl] + red[384 + rl]);
                    }
            }
        }
    }
}

// ---------------------------------------------------------------------------
extern "C" void kernel_launch(void* const* d_in, const int* in_sizes, int n_in,
                              void* d_out, int out_size) {
    const float* x = (const float*)d_in[0];
    float* out = (float*)d_out;

    prep_kernel<<<(B * N) / 8, 256>>>(x);

    cudaFuncSetAttribute(sim_mma_kernel,
                         cudaFuncAttributeMaxDynamicSharedMemorySize, SM_TOTAL);
    dim3 grid(N / 128, B);
    sim_mma_kernel<<<grid, 512, SM_TOTAL>>>(out);
}

// round 15
// speedup vs baseline: 1.1017x; 1.0003x over previous
#include <cuda_runtime.h>
#include <cuda_bf16.h>
#include <cstdint>

#define B 8
#define N 2048
#define D 128
#define TEMP (1.0f / 13.544f)
#define CLOG (-1.4426950408889634f * TEMP)        /* c = -T*log2(e) < 0 */
#define K2C  (2.0f * 1.4426950408889634f * TEMP)  /* -2c > 0 */

#define PSB 272            /* padded row stride in bytes (136 bf16) */
#define TILE_B 34816       /* 128 * PSB */

// smem layout (bytes)
#define SM_CSJ  0                      /* 2048 floats = 8192 B (all columns) */
#define SM_RED  8192                   /* 512 floats = 2048 B */
#define SM_A    10240
#define SM_B    (SM_A + TILE_B)        /* 4 ring buffers */
#define SM_TOTAL (SM_B + 4 * TILE_B)   /* 184320 */

__device__ __nv_bfloat16 g_xbf[B * N * D];
__device__ float g_sq[B * N];

// ---------------- helpers ----------------
__device__ __forceinline__ uint32_t smem_u32(const void* p) {
    uint32_t a;
    asm("{ .reg .u64 t; cvta.to.shared.u64 t, %1; cvt.u32.u64 %0, t; }"
        : "=r"(a) : "l"(p));
    return a;
}
__device__ __forceinline__ void ldsm_x4(uint32_t* r, uint32_t addr) {
    asm volatile("ldmatrix.sync.aligned.m8n8.x4.shared.b16 {%0,%1,%2,%3}, [%4];"
                 : "=r"(r[0]), "=r"(r[1]), "=r"(r[2]), "=r"(r[3]) : "r"(addr));
}
__device__ __forceinline__ void mma_16816(float* d, const uint32_t* a,
                                          const uint32_t* b) {
    asm volatile(
        "mma.sync.aligned.m16n8k16.row.col.f32.bf16.bf16.f32 "
        "{%0,%1,%2,%3}, {%4,%5,%6,%7}, {%8,%9}, {%0,%1,%2,%3};"
        : "+f"(d[0]), "+f"(d[1]), "+f"(d[2]), "+f"(d[3])
        : "r"(a[0]), "r"(a[1]), "r"(a[2]), "r"(a[3]), "r"(b[0]), "r"(b[1]));
}
__device__ __forceinline__ float ex2(float x) {
    float r;
    asm("ex2.approx.ftz.f32 %0, %1;" : "=f"(r) : "f"(x));
    return r;
}
#define CP16(saddr, gptr) \
    asm volatile("cp.async.cg.shared.global [%0], [%1], 16;" \
                 :: "r"(saddr), "l"(gptr))
#define CP_COMMIT() asm volatile("cp.async.commit_group;" ::: "memory")
#define CP_WAIT(n)  asm volatile("cp.async.wait_group %0;" :: "n"(n) : "memory")

// load A+B fragments for one k-step into the given phase buffers (R9 mapping)
__device__ __forceinline__ void load_frags(uint32_t arow, uint32_t bbase, int k,
                                           uint32_t af[2][4], uint32_t bf[4][2]) {
    ldsm_x4(af[0], arow + k * 32);
    ldsm_x4(af[1], arow + 16 * PSB + k * 32);
    uint32_t t[4];
    ldsm_x4(t, bbase + k * 32);
    bf[0][0] = t[0]; bf[0][1] = t[2];
    bf[1][0] = t[1]; bf[1][1] = t[3];
    ldsm_x4(t, bbase + 16 * PSB + k * 32);
    bf[2][0] = t[0]; bf[2][1] = t[2];
    bf[3][0] = t[1]; bf[3][1] = t[3];
}

// ---------------------------------------------------------------------------
// Prep: fp32 -> bf16 copy; squared norms from the bf16 values (fp32 accum)
// so the MMA diagonal distance cancels to ~0.
// ---------------------------------------------------------------------------
__global__ void prep_kernel(const float* __restrict__ x) {
    int row = blockIdx.x * 8 + (threadIdx.x >> 5);
    int lane = threadIdx.x & 31;
    float4 v = reinterpret_cast<const float4*>(x + (size_t)row * D)[lane];
    __nv_bfloat16 b0 = __float2bfloat16(v.x), b1 = __float2bfloat16(v.y);
    __nv_bfloat16 b2 = __float2bfloat16(v.z), b3 = __float2bfloat16(v.w);
    uint2 pk;
    pk.x = ((uint32_t)__bfloat16_as_ushort(b1) << 16) | __bfloat16_as_ushort(b0);
    pk.y = ((uint32_t)__bfloat16_as_ushort(b3) << 16) | __bfloat16_as_ushort(b2);
    reinterpret_cast<uint2*>(g_xbf + (size_t)row * D)[lane] = pk;
    float a0 = __bfloat162float(b0), a1 = __bfloat162float(b1);
    float a2 = __bfloat162float(b2), a3 = __bfloat162float(b3);
    float s = a0 * a0 + a1 * a1 + a2 * a2 + a3 * a3;
    #pragma unroll
    for (int o = 16; o; o >>= 1) s += __shfl_xor_sync(0xffffffffu, s, o);
    if (lane == 0) g_sq[row] = s;
}

// ---------------------------------------------------------------------------
// Main kernel: CTA = (batch, 128-row band). 16 warps (4x4), warp tile 32x32.
// 32 tiles = 16 j-tiles x 2 passes (pass 0 row sums, pass 1 store), processed
// as 16 super-iterations of TWO tiles per CP_WAIT+__syncthreads: prefetch for
// tiles 2ss+2/2ss+3 is issued AFTER the barrier (slots last read at ss-1 are
// provably free), and no barrier separates the two tiles' compute -> warps
// decorrelate and epilogue(tile0) overlaps MMA(tile1) across warps.
// ---------------------------------------------------------------------------
__global__ void __launch_bounds__(512, 1)
sim_mma_kernel(float* __restrict__ out) {
    extern __shared__ char smem[];
    const uint32_t sbase = smem_u32(smem);
    const int tid = threadIdx.x;
    const int wid = tid >> 5, lane = tid & 31;
    const int wm = wid & 3;                // 32-row band within 128
    const int wn = wid >> 2;               // 32-col band within 128
    const int b = blockIdx.y;
    const int i0 = blockIdx.x * 128;

    const __nv_bfloat16* xb = g_xbf + (size_t)b * N * D;
    const float* sqb = g_sq + b * N;
    float* csjall = reinterpret_cast<float*>(smem + SM_CSJ);
    float* red    = reinterpret_cast<float*>(smem + SM_RED);

    // ---- prologue: one group = A + B(0) + B(1); csj for all columns ----
    const int pr = tid >> 2, pc = tid & 3;        // 128 rows x 4 x 64B
    {
        const char* gA = (const char*)(xb + (size_t)(i0 + pr) * D) + pc * 64;
        uint32_t sA = sbase + SM_A + pr * PSB + pc * 64;
        const char* gB0 = (const char*)(xb + (size_t)pr * D) + pc * 64;
        uint32_t sB0 = sbase + SM_B + pr * PSB + pc * 64;
        const char* gB1 = (const char*)(xb + (size_t)(128 + pr) * D) + pc * 64;
        uint32_t sB1 = sbase + SM_B + TILE_B + pr * PSB + pc * 64;
        #pragma unroll
        for (int q = 0; q < 4; q++) {
            CP16(sA + q * 16, gA + q * 16);
            CP16(sB0 + q * 16, gB0 + q * 16);
            CP16(sB1 + q * 16, gB1 + q * 16);
        }
        CP_COMMIT();

        // csj for ALL 2048 columns (plain stores, covered by first sync)
        float4 sv = reinterpret_cast<const float4*>(sqb)[tid];
        float4 cv;
        cv.x = CLOG * sv.x; cv.y = CLOG * sv.y;
        cv.z = CLOG * sv.z; cv.w = CLOG * sv.w;
        reinterpret_cast<float4*>(csjall)[tid] = cv;
    }

    // per-thread row constants (LDG, independent of smem)
    float csi[2][2], inv[2][2], rsum[2][2];
    #pragma unroll
    for (int m = 0; m < 2; m++)
        #pragma unroll
        for (int s = 0; s < 2; s++) {
            int r = i0 + wm * 32 + m * 16 + (lane >> 2) + s * 8;
            csi[m][s] = CLOG * sqb[r];
            rsum[m][s] = 0.0f;
            inv[m][s] = 0.0f;
        }

    const uint32_t arow = sbase + SM_A + (wm * 32 + (lane & 15)) * PSB + (lane >> 4) * 16;
    const uint32_t bld  = sbase + SM_B + (wn * 32 + (lane & 15)) * PSB + (lane >> 4) * 16;

    for (int ss = 0; ss < 16; ss++) {
        CP_WAIT(0);          // B(2ss), B(2ss+1) (and A on ss=0) resident
        __syncthreads();     // + compute(ss-1) fully done on all warps

        // prefetch tiles 2ss+2, 2ss+3 into their ring slots (now provably free)
        if (ss < 15) {
            #pragma unroll
            for (int u = 0; u < 2; u++) {
                const int tile = 2 * ss + 2 + u;
                const int jn = (tile & 15) * 128;
                const char* gB = (const char*)(xb + (size_t)(jn + pr) * D) + pc * 64;
                uint32_t sB = sbase + SM_B + (tile & 3) * TILE_B + pr * PSB + pc * 64;
                #pragma unroll
                for (int q = 0; q < 4; q++) CP16(sB + q * 16, gB + q * 16);
            }
            CP_COMMIT();
        }

        // ---- two tiles, no barrier between them ----
        #pragma unroll
        for (int u = 0; u < 2; u++) {
            const int tile = 2 * ss + u;

            float acc[2][4][4];
            #pragma unroll
            for (int m = 0; m < 2; m++)
                #pragma unroll
                for (int n = 0; n < 4; n++)
                    #pragma unroll
                    for (int e = 0; e < 4; e++) acc[m][n][e] = 0.0f;

            const uint32_t bbase = bld + (tile & 3) * TILE_B;
            uint32_t af[2][2][4], bf[2][4][2];
            load_frags(arow, bbase, 0, af[0], bf[0]);
            #pragma unroll
            for (int k = 0; k < 8; k++) {
                const int cur = k & 1;
                if (k < 7) load_frags(arow, bbase, k + 1, af[cur ^ 1], bf[cur ^ 1]);
                #pragma unroll
                for (int m = 0; m < 2; m++)
                    #pragma unroll
                    for (int n = 0; n < 4; n++)
                        mma_16816(acc[m][n], af[cur][m], bf[cur][n]);
            }

            // ---- epilogue ----
            const int j0 = (tile & 15) * 128;
            const int colb = wn * 32 + (lane & 3) * 2;
            float cj[8];
            #pragma unroll
            for (int n = 0; n < 4; n++) {
                float2 t = *reinterpret_cast<const float2*>(csjall + j0 + colb + n * 8);
                cj[2 * n] = t.x; cj[2 * n + 1] = t.y;
            }

            if (tile < 16) {
                #pragma unroll
                for (int m = 0; m < 2; m++) {
                    float base0 = csi[m][0], base1 = csi[m][1];
                    #pragma unroll
                    for (int n = 0; n < 4; n++) {
                        float p0 = ex2(fmaf(K2C, acc[m][n][0], base0 + cj[2 * n]));
                        float p1 = ex2(fmaf(K2C, acc[m][n][1], base0 + cj[2 * n + 1]));
                        float p2 = ex2(fmaf(K2C, acc[m][n][2], base1 + cj[2 * n]));
                        float p3 = ex2(fmaf(K2C, acc[m][n][3], base1 + cj[2 * n + 1]));
                        rsum[m][0] += p0 + p1;
                        rsum[m][1] += p2 + p3;
                    }
                }
            } else {
                #pragma unroll
                for (int m = 0; m < 2; m++) {
                    const int r0 = i0 + wm * 32 + m * 16 + (lane >> 2);
                    float* orow0 = out + (size_t)(b * N + r0) * N + j0 + colb;
                    float* orow1 = orow0 + (size_t)8 * N;
                    float base0 = csi[m][0], base1 = csi[m][1];
                    #pragma unroll
                    for (int n = 0; n < 4; n++) {
                        float2 w0, w1;
                        w0.x = ex2(fmaf(K2C, acc[m][n][0], base0 + cj[2 * n]))     * inv[m][0];
                        w0.y = ex2(fmaf(K2C, acc[m][n][1], base0 + cj[2 * n + 1])) * inv[m][0];
                        w1.x = ex2(fmaf(K2C, acc[m][n][2], base1 + cj[2 * n]))     * inv[m][1];
                        w1.y = ex2(fmaf(K2C, acc[m][n][3], base1 + cj[2 * n + 1])) * inv[m][1];
                        *reinterpret_cast<float2*>(orow0 + n * 8) = w0;
                        *reinterpret_cast<float2*>(orow1 + n * 8) = w1;
                    }
                }
            }

            // ---- end of pass 0 (tile 15): reduce row sums across col bands ----
            if (tile == 15) {
                #pragma unroll
                for (int m = 0; m < 2; m++)
                    #pragma unroll
                    for (int s = 0; s < 2; s++) {
                        float v = rsum[m][s];
                        v += __shfl_xor_sync(0xffffffffu, v, 1);
                        v += __shfl_xor_sync(0xffffffffu, v, 2);
                        if ((lane & 3) == 0)
                            red[wn * 128 + wm * 32 + m * 16 + (lane >> 2) + s * 8] = v;
                    }
                __syncthreads();
                #pragma unroll
                for (int m = 0; m < 2; m++)
                    #pragma unroll
                    for (int s = 0; s < 2; s++) {
                        int rl = wm * 32 + m * 16 + (lane >> 2) + s * 8;
                        inv[m][s] = __fdividef(1.0f, red[rl] + red[128 + rl] +
                                                     red[256 + rl] + red[384 + rl]);
                    }
            }
        }
    }
}

// ---------------------------------------------------------------------------
extern "C" void kernel_launch(void* const* d_in, const int* in_sizes, int n_in,
                              void* d_out, int out_size) {
    const float* x = (const float*)d_in[0];
    float* out = (float*)d_out;

    prep_kernel<<<(B * N) / 8, 256>>>(x);

    cudaFuncSetAttribute(sim_mma_kernel,
                         cudaFuncAttributeMaxDynamicSharedMemorySize, SM_TOTAL);
    dim3 grid(N / 128, B);
    sim_mma_kernel<<<grid, 512, SM_TOTAL>>>(out);
}